// round 2
// baseline (speedup 1.0000x reference)
#include <cuda_runtime.h>
#include <math.h>

#define N_PTS 8192
#define D_DIM 256
#define NUM_CLS 64
#define EPSF  1e-10f

#define BM 128
#define BN 128
#define BK 16
#define TM 8
#define TN 8

// Scratch (device globals; no allocations allowed)
__device__ float g_sq[N_PTS];
__device__ float g_pos[N_PTS];
__device__ float g_neg[N_PTS];
__device__ int   g_cls[N_PTS];
__device__ int   g_tgt_is64;

// ---------------------------------------------------------------------------
// Kernel 0: detect target dtype (int32 vs int64) without OOB reads.
// Reads only the first 4096 int64 words = 32KB = exactly the int32 footprint.
// If data is int32, some high word is a nonzero class -> value >= NUM_CLS.
// ---------------------------------------------------------------------------
__global__ void detect_kernel(const long long* __restrict__ t) {
    __shared__ int bad;
    if (threadIdx.x == 0) bad = 0;
    __syncthreads();
    for (int i = threadIdx.x; i < N_PTS / 2; i += blockDim.x) {
        long long v = t[i];
        if (v < 0 || v >= (long long)NUM_CLS) bad = 1;  // benign race
    }
    __syncthreads();
    if (threadIdx.x == 0) g_tgt_is64 = !bad;
}

// ---------------------------------------------------------------------------
// Kernel 1: per-row squared norms, class load (dtype-adaptive), zero accums.
// One warp per row (D=256 -> 2 float4 per lane).
// ---------------------------------------------------------------------------
__global__ void prep_kernel(const float* __restrict__ pred,
                            const void* __restrict__ tgt) {
    int warp = (blockIdx.x * blockDim.x + threadIdx.x) >> 5;
    int lane = threadIdx.x & 31;
    if (warp >= N_PTS) return;
    const float4* row = (const float4*)(pred + (size_t)warp * D_DIM);
    float s = 0.f;
#pragma unroll
    for (int q = 0; q < 2; ++q) {
        float4 v = row[lane + 32 * q];
        s += v.x * v.x + v.y * v.y + v.z * v.z + v.w * v.w;
    }
#pragma unroll
    for (int o = 16; o; o >>= 1) s += __shfl_xor_sync(0xffffffffu, s, o);
    if (lane == 0) {
        g_sq[warp]  = s;
        g_pos[warp] = 0.f;
        g_neg[warp] = 0.f;
        int c;
        if (g_tgt_is64) c = (int)((const long long*)tgt)[warp];
        else            c = ((const int*)tgt)[warp];
        g_cls[warp] = c;
    }
}

// ---------------------------------------------------------------------------
// Kernel 2: fused tiled Gram + exp + masked column sums.
// Triangular: only tiles with bi <= bj computed; off-diagonal tiles feed
// both column-j sums and (via symmetry) column-i sums.
// ---------------------------------------------------------------------------
__global__ __launch_bounds__(256, 2)
void tile_kernel(const float* __restrict__ pred,
                 const float* __restrict__ tempPtr) {
    int bi = blockIdx.y, bj = blockIdx.x;
    if (bi > bj) return;

    __shared__ float As[BK][BM + 4];
    __shared__ float Bs[BK][BN + 4];
    __shared__ float sqR[BM], sqC[BN];
    __shared__ int   clR[BM], clC[BN];
    __shared__ float cPos[BN], cNeg[BN], rPos[BM], rNeg[BM];

    int tid = threadIdx.x;
    int tx = tid & 15, ty = tid >> 4;
    int i0 = bi * BM, j0 = bj * BN;

    if (tid < 128) {
        sqR[tid] = g_sq[i0 + tid];
        sqC[tid] = g_sq[j0 + tid];
        clR[tid] = g_cls[i0 + tid];
        clC[tid] = g_cls[j0 + tid];
        cPos[tid] = 0.f; cNeg[tid] = 0.f;
        rPos[tid] = 0.f; rNeg[tid] = 0.f;
    }

    float acc[TM][TN];
#pragma unroll
    for (int r = 0; r < TM; r++)
#pragma unroll
        for (int c = 0; c < TN; c++) acc[r][c] = 0.f;

#pragma unroll 1
    for (int kt = 0; kt < D_DIM / BK; ++kt) {
        int k0 = kt * BK;
        __syncthreads();  // previous compute done (also orders aux init)
#pragma unroll
        for (int h = 0; h < 2; ++h) {
            int f = tid + h * 256;          // 0..511 float4 slots per tile
            int row = f >> 2, q = f & 3;    // 4 float4 per row of 16 floats
            float4 va = *(const float4*)(pred + (size_t)(i0 + row) * D_DIM + k0 + q * 4);
            As[q * 4 + 0][row] = va.x; As[q * 4 + 1][row] = va.y;
            As[q * 4 + 2][row] = va.z; As[q * 4 + 3][row] = va.w;
            float4 vb = *(const float4*)(pred + (size_t)(j0 + row) * D_DIM + k0 + q * 4);
            Bs[q * 4 + 0][row] = vb.x; Bs[q * 4 + 1][row] = vb.y;
            Bs[q * 4 + 2][row] = vb.z; Bs[q * 4 + 3][row] = vb.w;
        }
        __syncthreads();
#pragma unroll
        for (int kk = 0; kk < BK; kk++) {
            float4 a0 = *(const float4*)&As[kk][ty * TM];
            float4 a1 = *(const float4*)&As[kk][ty * TM + 4];
            float4 b0 = *(const float4*)&Bs[kk][tx * TN];
            float4 b1 = *(const float4*)&Bs[kk][tx * TN + 4];
            float a[TM] = {a0.x, a0.y, a0.z, a0.w, a1.x, a1.y, a1.z, a1.w};
            float b[TN] = {b0.x, b0.y, b0.z, b0.w, b1.x, b1.y, b1.z, b1.w};
#pragma unroll
            for (int r = 0; r < TM; r++)
#pragma unroll
                for (int c = 0; c < TN; c++)
                    acc[r][c] = fmaf(a[r], b[c], acc[r][c]);
        }
    }
    __syncthreads();

    float invT = 1.0f / tempPtr[0];
    bool diag = (bi == bj);

    float colP[TN] = {0}, colN[TN] = {0}, rowP[TM] = {0}, rowN[TM] = {0};
#pragma unroll
    for (int r = 0; r < TM; r++) {
        int ii = ty * TM + r;
        float sqi = sqR[ii];
        int ci = clR[ii];
#pragma unroll
        for (int c = 0; c < TN; c++) {
            int jj = tx * TN + c;
            float pn = sqi + sqC[jj] - 2.0f * acc[r][c];
            pn = fmaxf(pn, EPSF);
            float dv = __expf(-pn * invT);
            if (diag && (ii == jj)) dv = 0.f;   // diagonal excluded by masks
            bool same = (ci == clC[jj]);
            float p = same ? dv : 0.f;
            float n = same ? 0.f : dv;
            colP[c] += p; colN[c] += n;
            rowP[r] += p; rowN[r] += n;
        }
    }
#pragma unroll
    for (int c = 0; c < TN; c++) {
        atomicAdd(&cPos[tx * TN + c], colP[c]);
        atomicAdd(&cNeg[tx * TN + c], colN[c]);
    }
    if (!diag) {
#pragma unroll
        for (int r = 0; r < TM; r++) {
            atomicAdd(&rPos[ty * TM + r], rowP[r]);
            atomicAdd(&rNeg[ty * TM + r], rowN[r]);
        }
    }
    __syncthreads();
    if (tid < 128) {
        atomicAdd(&g_pos[j0 + tid], cPos[tid]);
        atomicAdd(&g_neg[j0 + tid], cNeg[tid]);
        if (!diag) {
            atomicAdd(&g_pos[i0 + tid], rPos[tid]);
            atomicAdd(&g_neg[i0 + tid], rNeg[tid]);
        }
    }
}

// ---------------------------------------------------------------------------
// Kernel 3: final loss reduction (single block, deterministic).
// ---------------------------------------------------------------------------
__global__ void finalize_kernel(float* __restrict__ out) {
    __shared__ float red[256];
    int tid = threadIdx.x;
    float s = 0.f;
    for (int j = tid; j < N_PTS; j += 256) {
        float num = g_pos[j];
        float den = fmaxf(g_neg[j], EPSF);
        float frac = num / (num + den);
        if (frac >= EPSF) s += logf(frac);
    }
    red[tid] = s;
    __syncthreads();
    for (int o = 128; o; o >>= 1) {
        if (tid < o) red[tid] += red[tid + o];
        __syncthreads();
    }
    if (tid == 0) out[0] = -red[0] / (float)N_PTS;
}

// ---------------------------------------------------------------------------
extern "C" void kernel_launch(void* const* d_in, const int* in_sizes, int n_in,
                              void* d_out, int out_size) {
    const float* pred = (const float*)d_in[0];
    const void*  tgt  = d_in[1];
    const float* temp = (const float*)d_in[2];

    detect_kernel<<<1, 256>>>((const long long*)tgt);
    prep_kernel<<<(N_PTS * 32 + 255) / 256, 256>>>(pred, tgt);

    dim3 grid(N_PTS / BN, N_PTS / BM);
    tile_kernel<<<grid, 256>>>(pred, temp);

    finalize_kernel<<<1, 256>>>((float*)d_out);
}

// round 4
// speedup vs baseline: 3.5631x; 3.5631x over previous
#include <cuda_runtime.h>
#include <math.h>
#include <stdint.h>

#define N_PTS 8192
#define D_DIM 256
#define NUM_CLS 64
#define EPSF  1e-10f

#define BT 128                    // CTA tile M = N
#define BK 32                     // K chunk
#define NCHUNK (D_DIM / BK)       // 8
#define LDA 36                    // padded row stride (floats)
#define ABUF (BT * LDA)           // 4608 floats per stage per operand

__device__ float g_sq[N_PTS];
__device__ float g_pos[N_PTS];
__device__ float g_neg[N_PTS];
__device__ int   g_cls[N_PTS];
__device__ int   g_tgt_is64;

static __device__ __forceinline__ uint32_t smem_u32(const void* p) {
    uint32_t a;
    asm("{ .reg .u64 t; cvta.to.shared.u64 t, %1; cvt.u32.u64 %0, t; }"
        : "=r"(a) : "l"(p));
    return a;
}
static __device__ __forceinline__ void cp16(uint32_t dst, const void* src) {
    asm volatile("cp.async.cg.shared.global [%0], [%1], 16;"
                 :: "r"(dst), "l"(src) : "memory");
}
#define CP_COMMIT() asm volatile("cp.async.commit_group;" ::: "memory")
#define CP_WAIT(n)  asm volatile("cp.async.wait_group %0;" :: "n"(n) : "memory")

static __device__ __forceinline__ void mma_tf32(float* c, const uint32_t* a,
                                                const uint32_t* b) {
    asm volatile(
        "mma.sync.aligned.m16n8k8.row.col.f32.tf32.tf32.f32 "
        "{%0,%1,%2,%3}, {%4,%5,%6,%7}, {%8,%9}, {%0,%1,%2,%3};"
        : "+f"(c[0]), "+f"(c[1]), "+f"(c[2]), "+f"(c[3])
        : "r"(a[0]), "r"(a[1]), "r"(a[2]), "r"(a[3]), "r"(b[0]), "r"(b[1]));
}

// ---------------------------------------------------------------------------
// Kernel 0: detect target dtype (int32 vs int64) without OOB reads.
// ---------------------------------------------------------------------------
__global__ void detect_kernel(const long long* __restrict__ t) {
    __shared__ int bad;
    if (threadIdx.x == 0) bad = 0;
    __syncthreads();
    for (int i = threadIdx.x; i < N_PTS / 2; i += blockDim.x) {
        long long v = t[i];
        if (v < 0 || v >= (long long)NUM_CLS) bad = 1;  // benign race
    }
    __syncthreads();
    if (threadIdx.x == 0) g_tgt_is64 = !bad;
}

// ---------------------------------------------------------------------------
// Kernel 1: squared norms, class load (dtype-adaptive), zero accumulators.
// ---------------------------------------------------------------------------
__global__ void prep_kernel(const float* __restrict__ pred,
                            const void* __restrict__ tgt) {
    int warp = (blockIdx.x * blockDim.x + threadIdx.x) >> 5;
    int lane = threadIdx.x & 31;
    if (warp >= N_PTS) return;
    const float4* row = (const float4*)(pred + (size_t)warp * D_DIM);
    float s = 0.f;
#pragma unroll
    for (int q = 0; q < 2; ++q) {
        float4 v = row[lane + 32 * q];
        s += v.x * v.x + v.y * v.y + v.z * v.z + v.w * v.w;
    }
#pragma unroll
    for (int o = 16; o; o >>= 1) s += __shfl_xor_sync(0xffffffffu, s, o);
    if (lane == 0) {
        g_sq[warp]  = s;
        g_pos[warp] = 0.f;
        g_neg[warp] = 0.f;
        int c;
        if (g_tgt_is64) c = (int)((const long long*)tgt)[warp];
        else            c = ((const int*)tgt)[warp];
        g_cls[warp] = c;
    }
}

// ---------------------------------------------------------------------------
// Kernel 2: tf32 mma.sync Gram tile + fused epilogue (triangular+symmetric).
// ---------------------------------------------------------------------------
__global__ __launch_bounds__(256, 2)
void tile_kernel(const float* __restrict__ pred,
                 const float* __restrict__ tempPtr) {
    int bi = blockIdx.y, bj = blockIdx.x;
    if (bi > bj) return;

    extern __shared__ float sm[];
    float* As  = sm;                 // [2][BT][LDA]
    float* Bs  = sm + 2 * ABUF;      // [2][BT][LDA]
    float* sqR = sm + 4 * ABUF;
    float* sqC = sqR + BT;
    int*   clR = (int*)(sqC + BT);
    int*   clC = clR + BT;

    uint32_t sA = smem_u32(As), sB = smem_u32(Bs);

    int tid  = threadIdx.x;
    int lane = tid & 31, wid = tid >> 5;
    int wm = wid & 1, wn = wid >> 1;          // 2 x 4 warp grid
    int R0 = wm * 64, C0 = wn * 32;
    int gq = lane >> 2, tq = lane & 3;        // mma groupID / threadID
    int i0 = bi * BT, j0 = bj * BT;

    if (tid < BT) {
        sqR[tid] = g_sq[i0 + tid];
        sqC[tid] = g_sq[j0 + tid];
        clR[tid] = g_cls[i0 + tid];
        clC[tid] = g_cls[j0 + tid];
    }

    float acc[4][4][4];
#pragma unroll
    for (int mi = 0; mi < 4; mi++)
#pragma unroll
        for (int ni = 0; ni < 4; ni++)
#pragma unroll
            for (int v = 0; v < 4; v++) acc[mi][ni][v] = 0.f;

    // async copy of one K-chunk into stage buf
    auto issue = [&](int buf, int k0) {
#pragma unroll
        for (int i = 0; i < 4; ++i) {
            int f = tid + i * 256;            // 0..1023
            int row = f >> 3, q = f & 7;      // 8 x float4 per row
            uint32_t off = (uint32_t)(buf * ABUF + row * LDA + q * 4) * 4u;
            cp16(sA + off, pred + (size_t)(i0 + row) * D_DIM + k0 + q * 4);
            cp16(sB + off, pred + (size_t)(j0 + row) * D_DIM + k0 + q * 4);
        }
        CP_COMMIT();
    };

    issue(0, 0);
#pragma unroll 1
    for (int c = 0; c < NCHUNK; ++c) {
        if (c < NCHUNK - 1) {
            issue((c + 1) & 1, (c + 1) * BK);
            CP_WAIT(1);
        } else {
            CP_WAIT(0);
        }
        __syncthreads();
        const float* Ab = As + (c & 1) * ABUF;
        const float* Bb = Bs + (c & 1) * ABUF;
#pragma unroll
        for (int ks = 0; ks < 4; ++ks) {
            int kb = ks * 8 + tq;
            uint32_t a[4][4], b[4][2];
#pragma unroll
            for (int mi = 0; mi < 4; mi++) {
                int r = R0 + mi * 16 + gq;
                a[mi][0] = *(const uint32_t*)&Ab[r * LDA + kb];
                a[mi][1] = *(const uint32_t*)&Ab[(r + 8) * LDA + kb];
                a[mi][2] = *(const uint32_t*)&Ab[r * LDA + kb + 4];
                a[mi][3] = *(const uint32_t*)&Ab[(r + 8) * LDA + kb + 4];
            }
#pragma unroll
            for (int ni = 0; ni < 4; ni++) {
                int cn = C0 + ni * 8 + gq;
                b[ni][0] = *(const uint32_t*)&Bb[cn * LDA + kb];
                b[ni][1] = *(const uint32_t*)&Bb[cn * LDA + kb + 4];
            }
#pragma unroll
            for (int mi = 0; mi < 4; mi++)
#pragma unroll
                for (int ni = 0; ni < 4; ni++)
                    mma_tf32(acc[mi][ni], a[mi], b[ni]);
        }
        __syncthreads();   // compute done before next overwrite of this stage
    }

    // ---- Epilogue: exp + masked sums on register fragments ----
    float invT = 1.0f / tempPtr[0];
    bool diag  = (bi == bj);

    float rP[8], rN[8], cP[8], cN[8];
#pragma unroll
    for (int q = 0; q < 8; q++) { rP[q] = rN[q] = cP[q] = cN[q] = 0.f; }

#pragma unroll
    for (int mi = 0; mi < 4; mi++)
#pragma unroll
        for (int h = 0; h < 2; h++) {
            int rl = R0 + mi * 16 + gq + h * 8;
            float sqi = sqR[rl];
            int   ci  = clR[rl];
#pragma unroll
            for (int ni = 0; ni < 4; ni++)
#pragma unroll
                for (int w = 0; w < 2; w++) {
                    int cl = C0 + ni * 8 + tq * 2 + w;
                    float dot = acc[mi][ni][h * 2 + w];
                    float pn  = fmaxf(sqi + sqC[cl] - 2.0f * dot, EPSF);
                    float dv  = __expf(-pn * invT);
                    if (diag && rl == cl) dv = 0.f;
                    bool same = (ci == clC[cl]);
                    float p = same ? dv : 0.f;
                    float n = dv - p;
                    rP[mi * 2 + h] += p; rN[mi * 2 + h] += n;
                    cP[ni * 2 + w] += p; cN[ni * 2 + w] += n;
                }
        }

    // column sums: reduce across lanes sharing tq (xor 4,8,16)
#pragma unroll
    for (int q = 0; q < 8; q++) {
#pragma unroll
        for (int o = 4; o <= 16; o <<= 1) {
            cP[q] += __shfl_xor_sync(0xffffffffu, cP[q], o);
            cN[q] += __shfl_xor_sync(0xffffffffu, cN[q], o);
        }
    }
    if (lane < 4) {
#pragma unroll
        for (int q = 0; q < 8; q++) {
            int cl = C0 + (q >> 1) * 8 + lane * 2 + (q & 1);
            atomicAdd(&g_pos[j0 + cl], cP[q]);
            atomicAdd(&g_neg[j0 + cl], cN[q]);
        }
    }
    // row sums (symmetric contribution): reduce across lanes sharing gq (xor 1,2)
#pragma unroll
    for (int q = 0; q < 8; q++) {
#pragma unroll
        for (int o = 1; o <= 2; o <<= 1) {
            rP[q] += __shfl_xor_sync(0xffffffffu, rP[q], o);
            rN[q] += __shfl_xor_sync(0xffffffffu, rN[q], o);
        }
    }
    if (!diag && tq == 0) {
#pragma unroll
        for (int q = 0; q < 8; q++) {
            int rl = R0 + (q >> 1) * 16 + gq + (q & 1) * 8;
            atomicAdd(&g_pos[i0 + rl], rP[q]);
            atomicAdd(&g_neg[i0 + rl], rN[q]);
        }
    }
}

// ---------------------------------------------------------------------------
// Kernel 3: final loss reduction (single block, deterministic).
// ---------------------------------------------------------------------------
__global__ void finalize_kernel(float* __restrict__ out) {
    __shared__ float red[32];
    int tid = threadIdx.x;
    float s = 0.f;
    for (int j = tid; j < N_PTS; j += 1024) {
        float num = g_pos[j];
        float den = fmaxf(g_neg[j], EPSF);
        float frac = num / (num + den);
        if (frac >= EPSF) s += logf(frac);
    }
#pragma unroll
    for (int o = 16; o; o >>= 1) s += __shfl_xor_sync(0xffffffffu, s, o);
    if ((tid & 31) == 0) red[tid >> 5] = s;
    __syncthreads();
    if (tid < 32) {
        float v = red[tid];
#pragma unroll
        for (int o = 16; o; o >>= 1) v += __shfl_xor_sync(0xffffffffu, v, o);
        if (tid == 0) out[0] = -v / (float)N_PTS;
    }
}

// ---------------------------------------------------------------------------
extern "C" void kernel_launch(void* const* d_in, const int* in_sizes, int n_in,
                              void* d_out, int out_size) {
    const float* pred = (const float*)d_in[0];
    const void*  tgt  = d_in[1];
    const float* temp = (const float*)d_in[2];

    const int smem_bytes = (4 * ABUF + 2 * BT) * 4 + 2 * BT * 4;  // ~76 KB
    cudaFuncSetAttribute(tile_kernel,
                         cudaFuncAttributeMaxDynamicSharedMemorySize, smem_bytes);

    detect_kernel<<<1, 256>>>((const long long*)tgt);
    prep_kernel<<<(N_PTS * 32 + 255) / 256, 256>>>(pred, tgt);

    dim3 grid(N_PTS / BT, N_PTS / BT);
    tile_kernel<<<grid, 256, smem_bytes>>>(pred, temp);

    finalize_kernel<<<1, 1024>>>((float*)d_out);
}